// round 15
// baseline (speedup 1.0000x reference)
#include <cuda_runtime.h>
#include <cuda_fp16.h>
#include <stdint.h>

#define FFEAT   32
#define DDIM    64
#define P_PAIRS 496
#define FD      (FFEAT * DDIM)   // 2048
#define MT      128
#define THREADS 128

// smem: A[128][72] f16 (init only), staging[4][16][68] f32
#define APITCH 72
#define ROWB   (APITCH * 2)       // 144 B
#define SM_A   0
#define SM_ST  (SM_A + MT * ROWB)              // 18432
#define STPITCH 68
#define ST_WARP (16 * STPITCH * 4)             // 4352 B
#define SMEM_BYTES (SM_ST + 4 * ST_WARP)       // 35840  (4 CTAs: 143 KB)

// W in mma-fragment order: [p][kt(4)][np(4)][lane(32)] of uint4 (validated R13)
__device__ uint4 g_Wp[P_PAIRS * 16 * 32];

static __device__ __forceinline__ uint32_t smem_u32(const void* p) {
    uint32_t a;
    asm("{ .reg .u64 t; cvta.to.shared.u64 t, %1; cvt.u32.u64 %0, t; }" : "=r"(a) : "l"(p));
    return a;
}
static __device__ __forceinline__ uint32_t packh(float lo_e, float hi_e) {
    uint32_t r;
    asm("cvt.rn.f16x2.f32 %0, %1, %2;" : "=r"(r) : "f"(hi_e), "f"(lo_e));
    return r;
}

#define LDSM_X4(r, addr)                                                     \
    asm volatile("ldmatrix.sync.aligned.m8n8.x4.shared.b16 {%0,%1,%2,%3}, [%4];" \
        : "=r"((r)[0]), "=r"((r)[1]), "=r"((r)[2]), "=r"((r)[3]) : "r"(addr))
#define MMA16816(d, a, b0v, b1v)                                             \
    asm volatile("mma.sync.aligned.m16n8k16.row.col.f32.f16.f16.f32 "       \
        "{%0,%1,%2,%3},{%4,%5,%6,%7},{%8,%9},{%0,%1,%2,%3};"                 \
        : "+f"((d)[0]), "+f"((d)[1]), "+f"((d)[2]), "+f"((d)[3])             \
        : "r"((a)[0]), "r"((a)[1]), "r"((a)[2]), "r"((a)[3]),                \
          "r"(b0v), "r"(b1v))

// ---- prepass v2: one block per p, coalesced stage through smem ----
#define WP_PITCH 68
__global__ void wprep_kernel(const float* __restrict__ W) {
    __shared__ float sw[DDIM * WP_PITCH];
    const int p   = blockIdx.x;
    const int tid = threadIdx.x;   // 128
    const float4* wg = (const float4*)(W + (size_t)p * DDIM * DDIM);
    #pragma unroll
    for (int t = 0; t < 8; t++) {
        const int idx4 = tid + (t << 7);           // 0..1023
        const int k  = idx4 >> 4;
        const int n4 = (idx4 & 15) << 2;
        float4 v = wg[idx4];
        float* d = sw + k * WP_PITCH + n4;
        d[0] = v.x; d[1] = v.y; d[2] = v.z; d[3] = v.w;
    }
    __syncthreads();
    // 512 cells per p; 128 threads x 4 cells, consecutive writes coalesced
    uint4* dst = g_Wp + (size_t)p * (16 * 32);
    #pragma unroll
    for (int q = 0; q < 4; q++) {
        const int c  = tid + (q << 7);             // cell 0..511 = (kt*4+np)*32 + l
        const int l  = c & 31;
        const int np = (c >> 5) & 3;
        const int kt = c >> 7;
        const int k0 = kt * 16 + (l & 3) * 2;
        uint32_t r[4];
        #pragma unroll
        for (int h = 0; h < 2; h++) {
            const int n = (np * 2 + h) * 8 + (l >> 2);
            r[2 * h + 0] = packh(sw[k0 * WP_PITCH + n],       sw[(k0 + 1) * WP_PITCH + n]);
            r[2 * h + 1] = packh(sw[(k0 + 8) * WP_PITCH + n], sw[(k0 + 9) * WP_PITCH + n]);
        }
        dst[c] = make_uint4(r[0], r[1], r[2], r[3]);
    }
}

__global__ void __launch_bounds__(THREADS, 4)
bilin_hmma13(const float* __restrict__ X,   // [B, 32, 64]
             float* __restrict__ out)       // [B, 496, 64]
{
    extern __shared__ char smem[];
    const uint32_t sb  = smem_u32(smem);
    const int tid  = threadIdx.x;
    const int wid  = tid >> 5;
    const int lane = tid & 31;
    const int i    = blockIdx.y;
    const int b0   = blockIdx.x * MT;

    // ---- convert A = X[b0:b0+128, i, :] to f16 smem (warp-private rows) ----
    {
        const int m = tid;
        const float4* xr = (const float4*)(X + (size_t)(b0 + m) * FD + i * DDIM);
        char* ap = smem + SM_A + m * ROWB;
        #pragma unroll
        for (int q = 0; q < 16; q++) {
            float4 v = xr[q];
            *(uint2*)(ap + q * 8) = make_uint2(packh(v.x, v.y), packh(v.z, v.w));
        }
    }
    __syncwarp();

    // ---- A fragments in registers for the WHOLE j loop (32 regs) ----
    uint32_t a_h[2][4][4];
    {
        const int r16 = lane & 15;
        const int h16 = lane >> 4;
        #pragma unroll
        for (int mt = 0; mt < 2; mt++) {
            const int m = wid * 32 + mt * 16 + r16;
            #pragma unroll
            for (int kt = 0; kt < 4; kt++)
                LDSM_X4(a_h[mt][kt],
                        sb + SM_A + (uint32_t)(m * ROWB + kt * 32 + h16 * 16));
        }
    }

    const int pbase = i * (63 - i) / 2 - i - 1;   // p = pbase + j

    for (int j = i + 1; j < FFEAT; j++) {
        const int p = pbase + j;
        const uint4* wp = g_Wp + (size_t)p * (16 * 32) + lane;

        float acc[2][8][4];
        #pragma unroll
        for (int mt = 0; mt < 2; mt++)
            #pragma unroll
            for (int nt = 0; nt < 8; nt++)
                #pragma unroll
                for (int c = 0; c < 4; c++) acc[mt][nt][c] = 0.f;

        #pragma unroll
        for (int kt = 0; kt < 4; kt++) {
            uint4 bv[4];
            #pragma unroll
            for (int np = 0; np < 4; np++)
                bv[np] = wp[(kt * 4 + np) * 32];
            #pragma unroll
            for (int np = 0; np < 4; np++)
                #pragma unroll
                for (int mt = 0; mt < 2; mt++) {
                    MMA16816(acc[mt][2 * np + 0], a_h[mt][kt], bv[np].x, bv[np].y);
                    MMA16816(acc[mt][2 * np + 1], a_h[mt][kt], bv[np].z, bv[np].w);
                }
        }

        // ---- epilogue: stage D half-tile in smem, then coalesced xj/out ----
        {
            char* stw = smem + SM_ST + wid * ST_WARP;
            const int tr = lane >> 2;
            const int tc = (lane & 3) * 2;
            const int r2 = lane >> 4;
            const int c4 = (lane & 15) * 4;
            #pragma unroll
            for (int mt = 0; mt < 2; mt++) {
                // prefetch xj rows for first 4 s2-steps (overlaps staging)
                float4 xv[4];
                {
                    const int ma = b0 + wid * 32 + mt * 16 + r2;
                    #pragma unroll
                    for (int q = 0; q < 4; q++)
                        xv[q] = *(const float4*)(X + (size_t)(ma + 2 * q) * FD
                                                 + j * DDIM + c4);
                }
                __syncwarp();
                #pragma unroll
                for (int nt = 0; nt < 8; nt++) {
                    *(float2*)(stw + (tr * STPITCH + nt * 8 + tc) * 4) =
                        make_float2(acc[mt][nt][0], acc[mt][nt][1]);
                    *(float2*)(stw + ((tr + 8) * STPITCH + nt * 8 + tc) * 4) =
                        make_float2(acc[mt][nt][2], acc[mt][nt][3]);
                }
                __syncwarp();
                #pragma unroll
                for (int s2 = 0; s2 < 8; s2++) {
                    const int r  = s2 * 2 + r2;
                    const int m0 = b0 + wid * 32 + mt * 16 + r;
                    float4 d  = *(const float4*)(stw + (r * STPITCH + c4) * 4);
                    float4 x2;
                    if (s2 < 4) x2 = xv[s2];
                    else x2 = *(const float4*)(X + (size_t)m0 * FD + j * DDIM + c4);
                    float4 o = make_float4(d.x * x2.x, d.y * x2.y,
                                           d.z * x2.z, d.w * x2.w);
                    *(float4*)(out + ((size_t)m0 * P_PAIRS + p) * DDIM + c4) = o;
                }
            }
        }
    }
}

extern "C" void kernel_launch(void* const* d_in, const int* in_sizes, int n_in,
                              void* d_out, int out_size) {
    const float* X = (const float*)d_in[0];
    const float* W = (const float*)d_in[1];
    float* out = (float*)d_out;

    const int B = in_sizes[0] / FD;   // 4096

    wprep_kernel<<<P_PAIRS, 128>>>(W);

    cudaFuncSetAttribute(bilin_hmma13, cudaFuncAttributeMaxDynamicSharedMemorySize, SMEM_BYTES);
    dim3 grid(B / MT, FFEAT - 1);
    bilin_hmma13<<<grid, THREADS, SMEM_BYTES>>>(X, out);
}

// round 16
// speedup vs baseline: 1.1096x; 1.1096x over previous
#include <cuda_runtime.h>
#include <cuda_fp16.h>
#include <stdint.h>

#define FFEAT   32
#define DDIM    64
#define P_PAIRS 496
#define FD      (FFEAT * DDIM)   // 2048
#define MT      128
#define THREADS 256

// smem: A[128][72] f16 (init only), staging[8][16][40] f32
#define APITCH 72
#define ROWB   (APITCH * 2)       // 144 B
#define SM_A   0
#define SM_ST  (SM_A + MT * ROWB)              // 18432
#define STPITCH 40
#define ST_WARP (16 * STPITCH * 4)             // 2560 B
#define SMEM_BYTES (SM_ST + 8 * ST_WARP)       // 38912  (2 CTAs: 76 KB)

// W in mma-fragment order: [p][kt(4)][np(4)][lane(32)] of uint4 (validated R13)
__device__ uint4 g_Wp[P_PAIRS * 16 * 32];

static __device__ __forceinline__ uint32_t smem_u32(const void* p) {
    uint32_t a;
    asm("{ .reg .u64 t; cvta.to.shared.u64 t, %1; cvt.u32.u64 %0, t; }" : "=r"(a) : "l"(p));
    return a;
}
static __device__ __forceinline__ uint32_t packh(float lo_e, float hi_e) {
    uint32_t r;
    asm("cvt.rn.f16x2.f32 %0, %1, %2;" : "=r"(r) : "f"(hi_e), "f"(lo_e));
    return r;
}

#define LDSM_X4(r, addr)                                                     \
    asm volatile("ldmatrix.sync.aligned.m8n8.x4.shared.b16 {%0,%1,%2,%3}, [%4];" \
        : "=r"((r)[0]), "=r"((r)[1]), "=r"((r)[2]), "=r"((r)[3]) : "r"(addr))
#define MMA16816(d, a, b0v, b1v)                                             \
    asm volatile("mma.sync.aligned.m16n8k16.row.col.f32.f16.f16.f32 "       \
        "{%0,%1,%2,%3},{%4,%5,%6,%7},{%8,%9},{%0,%1,%2,%3};"                 \
        : "+f"((d)[0]), "+f"((d)[1]), "+f"((d)[2]), "+f"((d)[3])             \
        : "r"((a)[0]), "r"((a)[1]), "r"((a)[2]), "r"((a)[3]),                \
          "r"(b0v), "r"(b1v))

// ---- prepass (R14 version): W f32 [p][k][n] -> fragment-ordered f16 uint4 ----
__global__ void wprep_kernel(const float* __restrict__ W) {
    const int t = blockIdx.x * 256 + threadIdx.x;   // (p*16 + kt*4 + np)*32 + l
    const int l  = t & 31;
    const int np = (t >> 5) & 3;
    const int kt = (t >> 7) & 3;
    const int p  = t >> 9;
    const int k0 = kt * 16 + (l & 3) * 2;
    const float* wp = W + (size_t)p * DDIM * DDIM;
    uint32_t r[4];
    #pragma unroll
    for (int h = 0; h < 2; h++) {
        const int n = (np * 2 + h) * 8 + (l >> 2);
        r[2 * h + 0] = packh(wp[k0 * DDIM + n],       wp[(k0 + 1) * DDIM + n]);
        r[2 * h + 1] = packh(wp[(k0 + 8) * DDIM + n], wp[(k0 + 9) * DDIM + n]);
    }
    g_Wp[t] = make_uint4(r[0], r[1], r[2], r[3]);
}

__global__ void __launch_bounds__(THREADS, 2)
bilin_hmma14(const float* __restrict__ X,   // [B, 32, 64]
             float* __restrict__ out)       // [B, 496, 64]
{
    extern __shared__ char smem[];
    const uint32_t sb  = smem_u32(smem);
    const int tid  = threadIdx.x;
    const int wid  = tid >> 5;            // 0..7
    const int lane = tid & 31;
    const int rowg = wid >> 1;            // 0..3 : which 32 rows
    const int colh = wid & 1;             // 0..1 : which 32 cols
    const int i    = blockIdx.y;
    const int b0   = blockIdx.x * MT;

    // ---- convert A = X[b0:b0+128, i, :] to f16 smem (2 threads/row) ----
    {
        const int m  = tid >> 1;
        const int q0 = (tid & 1) * 8;
        const float4* xr = (const float4*)(X + (size_t)(b0 + m) * FD + i * DDIM) + q0;
        char* ap = smem + SM_A + m * ROWB + q0 * 8;
        #pragma unroll
        for (int q = 0; q < 8; q++) {
            float4 v = xr[q];
            *(uint2*)(ap + q * 8) = make_uint2(packh(v.x, v.y), packh(v.z, v.w));
        }
    }
    __syncthreads();

    // ---- A fragments in registers for the WHOLE j loop (32 regs) ----
    uint32_t a_h[2][4][4];
    {
        const int r16 = lane & 15;
        const int h16 = lane >> 4;
        #pragma unroll
        for (int mt = 0; mt < 2; mt++) {
            const int m = rowg * 32 + mt * 16 + r16;
            #pragma unroll
            for (int kt = 0; kt < 4; kt++)
                LDSM_X4(a_h[mt][kt],
                        sb + SM_A + (uint32_t)(m * ROWB + kt * 32 + h16 * 16));
        }
    }

    const int pbase = i * (63 - i) / 2 - i - 1;   // p = pbase + j

    for (int j = i + 1; j < FFEAT; j++) {
        const int p = pbase + j;
        const uint4* wp = g_Wp + (size_t)p * (16 * 32) + lane;

        float acc[2][4][4];   // [mt][local n-tile][c]
        #pragma unroll
        for (int mt = 0; mt < 2; mt++)
            #pragma unroll
            for (int nt = 0; nt < 4; nt++)
                #pragma unroll
                for (int c = 0; c < 4; c++) acc[mt][nt][c] = 0.f;

        #pragma unroll
        for (int kt = 0; kt < 4; kt++) {
            uint4 bv[2];
            #pragma unroll
            for (int h = 0; h < 2; h++)
                bv[h] = wp[(kt * 4 + colh * 2 + h) * 32];
            #pragma unroll
            for (int h = 0; h < 2; h++)
                #pragma unroll
                for (int mt = 0; mt < 2; mt++) {
                    MMA16816(acc[mt][2 * h + 0], a_h[mt][kt], bv[h].x, bv[h].y);
                    MMA16816(acc[mt][2 * h + 1], a_h[mt][kt], bv[h].z, bv[h].w);
                }
        }

        // ---- epilogue: stage 16x32 half-tile, then coalesced xj/out ----
        {
            char* stw = smem + SM_ST + wid * ST_WARP;
            const int tr = lane >> 2;            // 0..7
            const int tc = (lane & 3) * 2;       // 0..6
            const int rr = lane >> 3;            // 0..3 : read row within step
            const int c4 = (lane & 7) * 4;       // 0..28 : read col
            const int eg = colh * 32;            // global col base
            #pragma unroll
            for (int mt = 0; mt < 2; mt++) {
                // prefetch xj for first 2 read-steps (8 rows) to overlap staging
                float4 xv[2];
                {
                    const int ma = b0 + rowg * 32 + mt * 16 + rr;
                    xv[0] = *(const float4*)(X + (size_t)ma * FD + j * DDIM + eg + c4);
                    xv[1] = *(const float4*)(X + (size_t)(ma + 4) * FD + j * DDIM + eg + c4);
                }
                __syncwarp();
                #pragma unroll
                for (int nt = 0; nt < 4; nt++) {
                    *(float2*)(stw + (tr * STPITCH + nt * 8 + tc) * 4) =
                        make_float2(acc[mt][nt][0], acc[mt][nt][1]);
                    *(float2*)(stw + ((tr + 8) * STPITCH + nt * 8 + tc) * 4) =
                        make_float2(acc[mt][nt][2], acc[mt][nt][3]);
                }
                __syncwarp();
                #pragma unroll
                for (int s = 0; s < 4; s++) {
                    const int r  = s * 4 + rr;
                    const int m0 = b0 + rowg * 32 + mt * 16 + r;
                    float4 d  = *(const float4*)(stw + (r * STPITCH + c4) * 4);
                    float4 x2;
                    if (s < 2) x2 = xv[s];
                    else x2 = *(const float4*)(X + (size_t)m0 * FD + j * DDIM + eg + c4);
                    float4 o = make_float4(d.x * x2.x, d.y * x2.y,
                                           d.z * x2.z, d.w * x2.w);
                    *(float4*)(out + ((size_t)m0 * P_PAIRS + p) * DDIM + eg + c4) = o;
                }
            }
        }
    }
}

extern "C" void kernel_launch(void* const* d_in, const int* in_sizes, int n_in,
                              void* d_out, int out_size) {
    const float* X = (const float*)d_in[0];
    const float* W = (const float*)d_in[1];
    float* out = (float*)d_out;

    const int B = in_sizes[0] / FD;   // 4096

    wprep_kernel<<<P_PAIRS * 16 * 32 / 256, 256>>>(W);

    cudaFuncSetAttribute(bilin_hmma14, cudaFuncAttributeMaxDynamicSharedMemorySize, SMEM_BYTES);
    dim3 grid(B / MT, FFEAT - 1);
    bilin_hmma14<<<grid, THREADS, SMEM_BYTES>>>(X, out);
}